// round 3
// baseline (speedup 1.0000x reference)
#include <cuda_runtime.h>

// x: (64, 8, 32, 32) fp32. E=64 rows (1 center + 63 error terms),
// content = 8192 elements. Output = (1 + 63 + 8192) rows x 8192 = 270 MB.
#define N_CONTENT 8192
#define N_COL4    (N_CONTENT / 4)   // 2048
#define E_ROWS    64

// Scratch (__device__ globals; no allocation allowed)
__device__ int   g_flag[N_CONTENT];
__device__ float g_val[N_CONTENT];
__device__ int   g_col[N_CONTENT];   // per tail-row: target column k, or -1
__device__ float g_tval[N_CONTENT];  // per tail-row: value delta/2

// ---------------------------------------------------------------------------
// A) Fused zonotope ReLU: writes head row + 63 body rows (2 MB, single write),
//    and stashes per-k (flag, delta/2) for the tail.
// ---------------------------------------------------------------------------
__global__ void compute_kernel(const float* __restrict__ x, float* __restrict__ out) {
    int k = blockIdx.x * blockDim.x + threadIdx.x;
    if (k >= N_CONTENT) return;

    float c = x[k];
    float err = 0.f;
#pragma unroll 9
    for (int e = 1; e < E_ROWS; e++)
        err += fabsf(x[e * N_CONTENT + k]);     // coalesced; x (2 MB) is L2-resident

    float upper = c + err;
    float lower = c - err;

    float cross  = (lower * upper < 0.f) ? 1.f : 0.f;
    float nonneg = (lower >= 0.f) ? 1.f : 0.f;

    // Reference-exact: lam = nonneg + cross * upper/(upper-lower), NaN -> 0.5
    float lam = nonneg + cross * (upper / (upper - lower));
    if (isnan(lam)) lam = 0.5f;

    float delta = fmaxf(-lam * lower, (1.f - lam) * upper);

    // head (row 0)
    out[k] = (delta * 0.5f + lam * c) * cross + c * nonneg;

    // body (rows 1..63), second pass over x is L2-hot
    float mult = lam * cross + nonneg;
#pragma unroll 9
    for (int e = 1; e < E_ROWS; e++)
        out[e * N_CONTENT + k] = x[e * N_CONTENT + k] * mult;

    g_val[k]  = delta * 0.5f;
    g_flag[k] = (cross > 0.f) ? 1 : 0;
}

// ---------------------------------------------------------------------------
// B) 1-block exact scan of cross flags -> inverse row map:
//    for crossing k with exclusive prefix r: g_col[r] = k, g_tval[r] = val.
//    Rows without a target get g_col = -1.
// ---------------------------------------------------------------------------
__global__ void scan_kernel() {
    __shared__ int warp_sums[32];

    int tid  = threadIdx.x;          // 1024 threads
    int lane = tid & 31;
    int warp = tid >> 5;
    int base = tid * 8;              // 8 elements per thread -> 8192

    // init inverse map
#pragma unroll
    for (int i = 0; i < 8; i++) g_col[base + i] = -1;

    int flags[8];
    int local = 0;
#pragma unroll
    for (int i = 0; i < 8; i++) {
        flags[i] = g_flag[base + i];
        local += flags[i];
    }

    // warp inclusive scan of per-thread counts
    int v = local;
#pragma unroll
    for (int off = 1; off < 32; off <<= 1) {
        int n = __shfl_up_sync(0xffffffffu, v, off);
        if (lane >= off) v += n;
    }
    if (lane == 31) warp_sums[warp] = v;
    __syncthreads();

    if (warp == 0) {
        int w = warp_sums[lane];
#pragma unroll
        for (int off = 1; off < 32; off <<= 1) {
            int n = __shfl_up_sync(0xffffffffu, w, off);
            if (lane >= off) w += n;
        }
        warp_sums[lane] = w;
    }
    __syncthreads();   // also orders the g_col = -1 inits before the scatter below
    __threadfence_block();

    int excl = (v - local) + (warp > 0 ? warp_sums[warp - 1] : 0);

    int row = excl;
#pragma unroll
    for (int i = 0; i < 8; i++) {
        int k = base + i;
        if (flags[i]) {
            int r = min(row, N_CONTENT - 1);   // matches jnp.clip (can't trigger here)
            g_col[r]  = k;
            g_tval[r] = g_val[k];
            row++;
        }
    }
}

// ---------------------------------------------------------------------------
// C) Tail fill: one block per tail row streams zeros (coalesced float4 .cs
//    stores) and patches the row's single scatter target inline.
// ---------------------------------------------------------------------------
__global__ void zerotail_fused(float4* __restrict__ tail4) {
    int r = blockIdx.x;                       // 0..8191
    int t = threadIdx.x;                      // 256 threads

    int   k = __ldg(&g_col[r]);               // broadcast, L1-hot
    float v = (k >= 0) ? __ldg(&g_tval[r]) : 0.f;
    int kc4 = k >> 2;
    int kl  = k & 3;

    float4* row = tail4 + (long long)r * N_COL4;
#pragma unroll
    for (int j = 0; j < 8; j++) {
        int c4 = t + j * 256;                 // 0..2047, coalesced
        float4 z = make_float4(0.f, 0.f, 0.f, 0.f);
        if (k >= 0 && c4 == kc4) {            // rare (1 float4 per row)
            if      (kl == 0) z.x = v;
            else if (kl == 1) z.y = v;
            else if (kl == 2) z.z = v;
            else              z.w = v;
        }
        __stcs(row + c4, z);
    }
}

// ---------------------------------------------------------------------------
extern "C" void kernel_launch(void* const* d_in, const int* in_sizes, int n_in,
                              void* d_out, int out_size) {
    const float* x = (const float*)d_in[0];
    float* out = (float*)d_out;

    compute_kernel<<<(N_CONTENT + 255) / 256, 256>>>(x, out);
    scan_kernel<<<1, 1024>>>();

    float4* tail = (float4*)(out + (long long)E_ROWS * N_CONTENT);
    zerotail_fused<<<N_CONTENT, 256>>>(tail);
}

// round 4
// speedup vs baseline: 1.2336x; 1.2336x over previous
#include <cuda_runtime.h>

// x: (64, 8, 32, 32) fp32. 1 center + 63 error rows, content = 8192 elements.
// Output = (1 + 63 + 8192) x 8192 = 270 MB.
#define N_CONTENT 8192
#define N_COL4    (N_CONTENT / 4)   // 2048
#define E_ROWS    64
#define NBLK      32                // k-chunks of 256

// Scratch (__device__ globals; no allocation allowed)
__device__ float  g_errpart[8 * N_CONTENT];
__device__ float4 g_mult4[N_COL4];
__device__ float4 g_head4[N_COL4];
__device__ float  g_val[N_CONTENT];
__device__ int    g_flag[N_CONTENT];
__device__ int    g_blkcnt[NBLK];
__device__ int    g_blkoff[NBLK];
__device__ int    g_col[N_CONTENT];   // tail-row r -> column k (or -1)
__device__ float  g_tval[N_CONTENT];  // tail-row r -> value delta/2

// ---------------------------------------------------------------------------
// K1: partial abs-sums over e-slices (grid.x = 32 k-chunks, grid.y = 8 slices).
//     Also re-inits g_col to -1 every call (determinism).
// ---------------------------------------------------------------------------
__global__ void partial_kernel(const float* __restrict__ x) {
    int k = blockIdx.x * 256 + threadIdx.x;
    int s = blockIdx.y;                         // 0..7
    int e0 = (s == 0) ? 1 : s * 8;              // skip center row
    int e1 = s * 8 + 8;

    float p = 0.f;
#pragma unroll
    for (int e = e0; e < e1; e++)
        p += fabsf(x[e * N_CONTENT + k]);
    g_errpart[s * N_CONTENT + k] = p;

    if (s == 0) g_col[k] = -1;
}

// ---------------------------------------------------------------------------
// K2: per-k scalars + per-block crossing counts. 32 blocks x 256.
// ---------------------------------------------------------------------------
__global__ void scalars_kernel(const float* __restrict__ x) {
    __shared__ int wcnt[8];
    int tid = threadIdx.x;
    int k = blockIdx.x * 256 + tid;

    float err = 0.f;
#pragma unroll
    for (int s = 0; s < 8; s++)
        err += g_errpart[s * N_CONTENT + k];

    float c = x[k];
    float upper = c + err;
    float lower = c - err;

    float cross  = (lower * upper < 0.f) ? 1.f : 0.f;
    float nonneg = (lower >= 0.f) ? 1.f : 0.f;

    // Reference-exact: lam = nonneg + cross*upper/(upper-lower), NaN -> 0.5
    float lam = nonneg + cross * (upper / (upper - lower));
    if (isnan(lam)) lam = 0.5f;

    float delta = fmaxf(-lam * lower, (1.f - lam) * upper);

    ((float*)g_mult4)[k] = lam * cross + nonneg;
    ((float*)g_head4)[k] = (delta * 0.5f + lam * c) * cross + c * nonneg;
    g_val[k]  = delta * 0.5f;
    int f = (cross > 0.f) ? 1 : 0;
    g_flag[k] = f;

    // block crossing count
    int bc = __popc(__ballot_sync(0xffffffffu, f));
    if ((tid & 31) == 0) wcnt[tid >> 5] = bc;
    __syncthreads();
    if (tid == 0) {
        int s = 0;
#pragma unroll
        for (int w = 0; w < 8; w++) s += wcnt[w];
        g_blkcnt[blockIdx.x] = s;
    }
}

// ---------------------------------------------------------------------------
// K3: 1 warp scans the 32 block counts -> exclusive offsets.
// ---------------------------------------------------------------------------
__global__ void blockscan_kernel() {
    int lane = threadIdx.x;                     // 32 threads
    int v = g_blkcnt[lane];
    int incl = v;
#pragma unroll
    for (int off = 1; off < 32; off <<= 1) {
        int n = __shfl_up_sync(0xffffffffu, incl, off);
        if (lane >= off) incl += n;
    }
    g_blkoff[lane] = incl - v;                  // exclusive
}

// ---------------------------------------------------------------------------
// K4: inverse map. 32 blocks x 256: block-local exclusive scan of flags,
//     add block offset, write g_col[r]=k, g_tval[r]=delta/2 for crossings.
// ---------------------------------------------------------------------------
__global__ void invmap_kernel() {
    __shared__ int wsum[8];
    int tid  = threadIdx.x;
    int lane = tid & 31;
    int warp = tid >> 5;
    int k = blockIdx.x * 256 + tid;

    int f = g_flag[k];

    unsigned bal = __ballot_sync(0xffffffffu, f);
    int warp_excl = __popc(bal & ((1u << lane) - 1u));
    if (lane == 31) wsum[warp] = __popc(bal);
    __syncthreads();

    int wpre = 0;
#pragma unroll
    for (int w = 0; w < 8; w++)
        if (w < warp) wpre += wsum[w];

    if (f) {
        int r = g_blkoff[blockIdx.x] + wpre + warp_excl;
        r = min(r, N_CONTENT - 1);              // matches jnp.clip
        g_col[r]  = k;
        g_tval[r] = g_val[k];
    }
}

// ---------------------------------------------------------------------------
// K5: mega-fill — entire 270 MB output in one chip-wide pass.
//     block = one output row (8256 blocks x 256 threads, 8 float4 each).
// ---------------------------------------------------------------------------
__global__ void fill_kernel(const float4* __restrict__ x4, float4* __restrict__ out4) {
    int r = blockIdx.x;
    int t = threadIdx.x;
    float4* row = out4 + (long long)r * N_COL4;

    if (r == 0) {
#pragma unroll
        for (int j = 0; j < 8; j++) {
            int c4 = t + j * 256;
            row[c4] = g_head4[c4];
        }
    } else if (r < E_ROWS) {
        const float4* xr = x4 + (long long)r * N_COL4;
#pragma unroll
        for (int j = 0; j < 8; j++) {
            int c4 = t + j * 256;
            float4 v = xr[c4];                  // L2-hot (K1 read it)
            float4 m = g_mult4[c4];
            v.x *= m.x; v.y *= m.y; v.z *= m.z; v.w *= m.w;
            row[c4] = v;
        }
    } else {
        int tr = r - E_ROWS;                    // tail row
        int   k = -1;
        float v = 0.f;
        if (t == 0) {                           // patch data (latency hidden by zero loop)
            k = g_col[tr];
            if (k >= 0) v = g_tval[tr];
        }
        float4 z = make_float4(0.f, 0.f, 0.f, 0.f);
#pragma unroll
        for (int j = 0; j < 8; j++)
            __stcs(row + (t + j * 256), z);
        __syncthreads();                        // order patch after zeros
        if (t == 0 && k >= 0)
            ((float*)row)[k] = v;
    }
}

// ---------------------------------------------------------------------------
extern "C" void kernel_launch(void* const* d_in, const int* in_sizes, int n_in,
                              void* d_out, int out_size) {
    const float* x = (const float*)d_in[0];
    float* out = (float*)d_out;

    dim3 g1(NBLK, 8);
    partial_kernel<<<g1, 256>>>(x);
    scalars_kernel<<<NBLK, 256>>>(x);
    blockscan_kernel<<<1, 32>>>();
    invmap_kernel<<<NBLK, 256>>>();

    int total_rows = 1 + (E_ROWS - 1) + N_CONTENT;   // 8256
    fill_kernel<<<total_rows, 256>>>((const float4*)x, (float4*)out);
}

// round 5
// speedup vs baseline: 1.3472x; 1.0921x over previous
#include <cuda_runtime.h>

// x: (64, 8, 32, 32) fp32. 1 center + 63 error rows, content = 8192 elements.
// Output = (1 + 63 + 8192) x 8192 = 270 MB.
#define N_CONTENT 8192
#define N_COL4    (N_CONTENT / 4)   // 2048
#define E_ROWS    64
#define NCHUNK    128               // 8192 / 64 k's per chunk

// Scratch (__device__ globals; no allocation allowed)
__device__ float4   g_mult4[N_COL4];
__device__ float4   g_head4[N_COL4];
__device__ float    g_val[N_CONTENT];
__device__ unsigned g_mask[2 * NCHUNK];   // crossing-flag bitmask, 64 bits/chunk

// ---------------------------------------------------------------------------
// K1: prep — err reduction (4 threads per k), per-k scalars, flag bitmasks.
//     128 blocks x 256 threads; each block owns 64 consecutive k's.
// ---------------------------------------------------------------------------
__global__ void prep_kernel(const float* __restrict__ x) {
    __shared__ float s_err[4][64];

    int t  = threadIdx.x;
    int kk = t & 63;
    int sl = t >> 6;                       // e-slice 0..3 (16 rows each)
    int k  = blockIdx.x * 64 + kk;

    int e0 = sl * 16 + (sl == 0 ? 1 : 0);  // skip center row
    int e1 = sl * 16 + 16;

    float p = 0.f;
#pragma unroll
    for (int e = e0; e < e1; e++)
        p += fabsf(x[e * N_CONTENT + k]);  // coalesced per warp
    s_err[sl][kk] = p;
    __syncthreads();

    if (t < 64) {                          // warps 0 and 1, fully active
        int kb = blockIdx.x * 64 + t;
        float err = s_err[0][t] + s_err[1][t] + s_err[2][t] + s_err[3][t];
        float c = x[kb];

        float upper = c + err;
        float lower = c - err;

        float cross  = (lower * upper < 0.f) ? 1.f : 0.f;
        float nonneg = (lower >= 0.f) ? 1.f : 0.f;

        // Reference-exact: lam = nonneg + cross*upper/(upper-lower), NaN -> 0.5
        float lam = nonneg + cross * (upper / (upper - lower));
        if (isnan(lam)) lam = 0.5f;

        float delta = fmaxf(-lam * lower, (1.f - lam) * upper);

        ((float*)g_mult4)[kb] = lam * cross + nonneg;
        ((float*)g_head4)[kb] = (delta * 0.5f + lam * c) * cross + c * nonneg;
        g_val[kb] = delta * 0.5f;

        int f = (cross > 0.f) ? 1 : 0;
        unsigned bal = __ballot_sync(0xffffffffu, f);
        if ((t & 31) == 0)
            g_mask[blockIdx.x * 2 + (t >> 5)] = bal;
    }
}

// ---------------------------------------------------------------------------
// K2: mega-fill — entire 270 MB in one chip-wide pass, one block per row.
//     Tail rows resolve their own scatter target from the chunk bitmasks;
//     the ~1 KB search is hidden under the row's 32 KB of streaming stores.
// ---------------------------------------------------------------------------
__global__ void fill_kernel(const float4* __restrict__ x4, float4* __restrict__ out4) {
    int r = blockIdx.x;
    int t = threadIdx.x;
    float4* row = out4 + (long long)r * N_COL4;

    if (r == 0) {
#pragma unroll
        for (int j = 0; j < 8; j++) {
            int c4 = t + j * 256;
            row[c4] = g_head4[c4];
        }
        return;
    }
    if (r < E_ROWS) {
        const float4* xr = x4 + (long long)r * N_COL4;
#pragma unroll
        for (int j = 0; j < 8; j++) {
            int c4 = t + j * 256;
            float4 v = xr[c4];              // L2-hot
            float4 m = g_mult4[c4];
            v.x *= m.x; v.y *= m.y; v.z *= m.z; v.w *= m.w;
            row[c4] = v;
        }
        return;
    }

    // ---- tail row ----
    __shared__ int s_wtot[4];
    int tr = r - E_ROWS;                    // target row index in tail
    int lane = t & 31;
    int w = t >> 5;

    unsigned m0 = 0, m1 = 0;
    int cnt = 0, incl = 0;
    if (t < NCHUNK) {                       // warps 0..3, fully active
        m0 = g_mask[2 * t];
        m1 = g_mask[2 * t + 1];
        cnt = __popc(m0) + __popc(m1);
        incl = cnt;
#pragma unroll
        for (int off = 1; off < 32; off <<= 1) {
            int n = __shfl_up_sync(0xffffffffu, incl, off);
            if (lane >= off) incl += n;
        }
        if (lane == 31) s_wtot[w] = incl;
    }
    __syncthreads();

    int kfound = -1;
    float vfound = 0.f;
    if (t < NCHUNK) {
        int wo = 0;
#pragma unroll
        for (int w2 = 0; w2 < 4; w2++)
            if (w2 < w) wo += s_wtot[w2];
        int excl = wo + incl - cnt;         // crossings before this chunk
        if (tr >= excl && tr < excl + cnt) {
            int i = tr - excl;              // 0-indexed within chunk
            int p0 = __popc(m0);
            int pos = (i < p0) ? (int)__fns(m0, 0, i + 1)
                               : 32 + (int)__fns(m1, 0, i - p0 + 1);
            kfound = t * 64 + pos;
            vfound = g_val[kfound];
        }
    }

    // stream zeros over the whole row
    float4 z = make_float4(0.f, 0.f, 0.f, 0.f);
#pragma unroll
    for (int j = 0; j < 8; j++)
        __stcs(row + (t + j * 256), z);
    __syncthreads();                        // order patch after zeros

    if (kfound >= 0)
        ((float*)row)[kfound] = vfound;
}

// ---------------------------------------------------------------------------
extern "C" void kernel_launch(void* const* d_in, const int* in_sizes, int n_in,
                              void* d_out, int out_size) {
    const float* x = (const float*)d_in[0];
    float* out = (float*)d_out;

    prep_kernel<<<NCHUNK, 256>>>(x);

    int total_rows = E_ROWS + N_CONTENT;    // 8256
    fill_kernel<<<total_rows, 256>>>((const float4*)x, (float4*)out);
}